// round 3
// baseline (speedup 1.0000x reference)
#include <cuda_runtime.h>

// Problem constants (fixed by the reference)
constexpr int kB = 2, kS = 2048, kH = 32, kHK = 8, kD = 128;
constexpr int kG  = kH / kHK;     // 4
constexpr int kN  = kB * kS;      // 4096
constexpr int kHD = kH * kD;      // 4096
constexpr int kHKD = kHK * kD;    // 1024
constexpr float kScale = 0.08838834764831845f;  // 1/sqrt(128)

// Tiling
constexpr int BM = 64, BN = 64, NT = 256;
constexpr int PN = 68;  // padded pitch for P tile (kills STS bank conflicts)
constexpr int SMEM_FLOATS = kD * BM + kD * BN + BN * kD + BM * PN + 3 * BM;
constexpr int SMEM_BYTES  = SMEM_FLOATS * 4;  // ~116.5 KB

// ---------------------------------------------------------------------------
// KV-cache: copy old cache into output, then scatter fresh K/V rows by slot.
// ---------------------------------------------------------------------------
__global__ void cache_copy_kernel(const float* __restrict__ kc,
                                  const float* __restrict__ vc,
                                  float* __restrict__ okc,
                                  float* __restrict__ ovc) {
    int i = blockIdx.x * blockDim.x + threadIdx.x;
    int n4 = kN * kHKD / 4;
    if (i < n4) {
        reinterpret_cast<float4*>(okc)[i] = reinterpret_cast<const float4*>(kc)[i];
        reinterpret_cast<float4*>(ovc)[i] = reinterpret_cast<const float4*>(vc)[i];
    }
}

__global__ void cache_scatter_kernel(const float* __restrict__ k,
                                     const float* __restrict__ v,
                                     const int* __restrict__ slot,
                                     float* __restrict__ okc,
                                     float* __restrict__ ovc) {
    int i = blockIdx.x * blockDim.x + threadIdx.x;  // over N * HKD/4
    constexpr int per_row = kHKD / 4;
    int n4 = kN * per_row;
    if (i < n4) {
        int n = i / per_row;
        int c = i - n * per_row;
        int s = slot[n];
        if (s >= 0 && s < kN) {
            reinterpret_cast<float4*>(okc)[s * per_row + c] =
                reinterpret_cast<const float4*>(k)[i];
            reinterpret_cast<float4*>(ovc)[s * per_row + c] =
                reinterpret_cast<const float4*>(v)[i];
        }
    }
}

// ---------------------------------------------------------------------------
// Flash attention, fp32 FFMA, online softmax.
// Grid: (S/BM, H, B). One CTA = 64 queries of one head.
// ---------------------------------------------------------------------------
__global__ __launch_bounds__(NT, 2)
void attn_kernel(const float* __restrict__ q, const float* __restrict__ k,
                 const float* __restrict__ v, float* __restrict__ o) {
    extern __shared__ float sm[];
    float* Qt  = sm;               // [D][BM] d-major (transposed)
    float* Kt  = Qt + kD * BM;     // [D][BN] d-major (transposed)
    float* Vs  = Kt + kD * BN;     // [BN][D] row-major
    float* Ps  = Vs + BN * kD;     // [BM][PN]
    float* smM = Ps + BM * PN;     // running max  [BM]
    float* smL = smM + BM;         // running sum  [BM]
    float* smA = smL + BM;         // per-tile rescale [BM]

    const int tid = threadIdx.x;
    const int qb = blockIdx.x, h = blockIdx.y, b = blockIdx.z;
    const int hk = h / kG;

    // GEMM1 thread map: (ty,tx) in 16x16, micro-tile 4x4
    const int ty = tid >> 4, tx = tid & 15;
    // GEMM2 thread map: warp wr owns 8 rows, lane lc owns 4 cols
    const int wr = tid >> 5, lc = tid & 31;

    // ---- Load Q transposed (lane = row -> conflict-free scalar STS) ----
    const float* qbase = q + (size_t)(b * kS + qb * BM) * kHD + h * kD;
    #pragma unroll
    for (int it = 0; it < (BM * (kD / 4)) / NT; ++it) {  // 8 iters
        int idx = it * NT + tid;
        int r   = idx & (BM - 1);
        int c4  = idx >> 6;
        float4 val = *reinterpret_cast<const float4*>(qbase + r * kHD + c4 * 4);
        Qt[(c4 * 4 + 0) * BM + r] = val.x;
        Qt[(c4 * 4 + 1) * BM + r] = val.y;
        Qt[(c4 * 4 + 2) * BM + r] = val.z;
        Qt[(c4 * 4 + 3) * BM + r] = val.w;
    }
    if (tid < BM) { smM[tid] = -1e30f; smL[tid] = 0.f; }

    float oacc[8][4];
    #pragma unroll
    for (int i = 0; i < 8; ++i)
        #pragma unroll
        for (int j = 0; j < 4; ++j) oacc[i][j] = 0.f;

    for (int kt = 0; kt <= qb; ++kt) {
        __syncthreads();  // protect Kt/Vs/Ps from previous iteration's readers

        // ---- Load K transposed + V row-major ----
        const float* kbase = k + (size_t)(b * kS + kt * BN) * kHKD + hk * kD;
        const float* vbase = v + (size_t)(b * kS + kt * BN) * kHKD + hk * kD;
        #pragma unroll
        for (int it = 0; it < (BN * (kD / 4)) / NT; ++it) {
            int idx = it * NT + tid;
            int r   = idx & (BN - 1);
            int c4  = idx >> 6;
            float4 val = *reinterpret_cast<const float4*>(kbase + r * kHKD + c4 * 4);
            Kt[(c4 * 4 + 0) * BN + r] = val.x;
            Kt[(c4 * 4 + 1) * BN + r] = val.y;
            Kt[(c4 * 4 + 2) * BN + r] = val.z;
            Kt[(c4 * 4 + 3) * BN + r] = val.w;
        }
        #pragma unroll
        for (int it = 0; it < (BN * (kD / 4)) / NT; ++it) {
            int idx = it * NT + tid;
            int d4  = idx & 31;
            int r   = idx >> 5;
            *reinterpret_cast<float4*>(&Vs[r * kD + d4 * 4]) =
                *reinterpret_cast<const float4*>(vbase + r * kHKD + d4 * 4);
        }
        __syncthreads();

        // ---- GEMM1: S[64][64] = Q · K^T (both operands d-major) ----
        float acc[4][4];
        #pragma unroll
        for (int i = 0; i < 4; ++i)
            #pragma unroll
            for (int j = 0; j < 4; ++j) acc[i][j] = 0.f;

        #pragma unroll 4
        for (int d = 0; d < kD; ++d) {
            float4 qv = *reinterpret_cast<const float4*>(&Qt[d * BM + 4 * ty]);
            float4 kv = *reinterpret_cast<const float4*>(&Kt[d * BN + 4 * tx]);
            float qa[4] = {qv.x, qv.y, qv.z, qv.w};
            float ka[4] = {kv.x, kv.y, kv.z, kv.w};
            #pragma unroll
            for (int i = 0; i < 4; ++i)
                #pragma unroll
                for (int j = 0; j < 4; ++j) acc[i][j] += qa[i] * ka[j];
        }

        // ---- Online softmax (row groups = 16 lanes sharing ty) ----
        const bool diag = (kt == qb);
        const int qi0 = qb * BM + 4 * ty;
        const int ki0 = kt * BN + 4 * tx;
        #pragma unroll
        for (int i = 0; i < 4; ++i) {
            int r = 4 * ty + i;
            float rm = -1e30f;
            #pragma unroll
            for (int j = 0; j < 4; ++j) {
                float sc = acc[i][j] * kScale;
                if (diag && (ki0 + j > qi0 + i)) sc = -1e30f;
                acc[i][j] = sc;
                rm = fmaxf(rm, sc);
            }
            #pragma unroll
            for (int off = 8; off >= 1; off >>= 1)
                rm = fmaxf(rm, __shfl_xor_sync(0xffffffffu, rm, off));
            float mold = smM[r];
            float mnew = fmaxf(mold, rm);
            float rs = 0.f;
            #pragma unroll
            for (int j = 0; j < 4; ++j) {
                float p = __expf(acc[i][j] - mnew);
                acc[i][j] = p;
                rs += p;
            }
            #pragma unroll
            for (int off = 8; off >= 1; off >>= 1)
                rs += __shfl_xor_sync(0xffffffffu, rs, off);
            float alpha = __expf(mold - mnew);
            __syncwarp();  // all lanes finished reading smM[r]/smL[r]
            if (tx == 0) {
                smM[r] = mnew;
                smL[r] = smL[r] * alpha + rs;
                smA[r] = alpha;
            }
            float4 pv = {acc[i][0], acc[i][1], acc[i][2], acc[i][3]};
            *reinterpret_cast<float4*>(&Ps[r * PN + 4 * tx]) = pv;
        }
        __syncthreads();

        // ---- GEMM2: O += P · V, with online rescale ----
        #pragma unroll
        for (int i = 0; i < 8; ++i) {
            float a = smA[wr * 8 + i];
            #pragma unroll
            for (int j = 0; j < 4; ++j) oacc[i][j] *= a;
        }
        #pragma unroll 2
        for (int kk = 0; kk < BN / 4; ++kk) {
            float4 vv0 = *reinterpret_cast<const float4*>(&Vs[(4 * kk + 0) * kD + 4 * lc]);
            float4 vv1 = *reinterpret_cast<const float4*>(&Vs[(4 * kk + 1) * kD + 4 * lc]);
            float4 vv2 = *reinterpret_cast<const float4*>(&Vs[(4 * kk + 2) * kD + 4 * lc]);
            float4 vv3 = *reinterpret_cast<const float4*>(&Vs[(4 * kk + 3) * kD + 4 * lc]);
            #pragma unroll
            for (int i = 0; i < 8; ++i) {
                float4 pv = *reinterpret_cast<const float4*>(&Ps[(wr * 8 + i) * PN + 4 * kk]);
                oacc[i][0] += pv.x * vv0.x + pv.y * vv1.x + pv.z * vv2.x + pv.w * vv3.x;
                oacc[i][1] += pv.x * vv0.y + pv.y * vv1.y + pv.z * vv2.y + pv.w * vv3.y;
                oacc[i][2] += pv.x * vv0.z + pv.y * vv1.z + pv.z * vv2.z + pv.w * vv3.z;
                oacc[i][3] += pv.x * vv0.w + pv.y * vv1.w + pv.z * vv2.w + pv.w * vv3.w;
            }
        }
    }

    // ---- Epilogue: divide by l, write O ----
    float* obase = o + (size_t)(b * kS + qb * BM) * kHD + h * kD;
    #pragma unroll
    for (int i = 0; i < 8; ++i) {
        int r = wr * 8 + i;
        float inv = 1.0f / smL[r];
        float4 ov = {oacc[i][0] * inv, oacc[i][1] * inv,
                     oacc[i][2] * inv, oacc[i][3] * inv};
        *reinterpret_cast<float4*>(obase + r * kHD + 4 * lc) = ov;
    }
}

// ---------------------------------------------------------------------------
// Launch: output buffer = [ o (N*H*D) | k_cache (N*HK*D) | v_cache (N*HK*D) ]
// ---------------------------------------------------------------------------
extern "C" void kernel_launch(void* const* d_in, const int* in_sizes, int n_in,
                              void* d_out, int out_size) {
    const float* q    = (const float*)d_in[0];
    const float* k    = (const float*)d_in[1];
    const float* v    = (const float*)d_in[2];
    const float* kc   = (const float*)d_in[3];
    const float* vc   = (const float*)d_in[4];
    const int*   slot = (const int*)d_in[5];

    float* out    = (float*)d_out;
    float* out_o  = out;
    float* out_kc = out + (size_t)kN * kHD;
    float* out_vc = out_kc + (size_t)kN * kHKD;

    cudaFuncSetAttribute(attn_kernel,
                         cudaFuncAttributeMaxDynamicSharedMemorySize, SMEM_BYTES);

    int n4 = kN * kHKD / 4;
    cache_copy_kernel<<<(n4 + 255) / 256, 256>>>(kc, vc, out_kc, out_vc);
    cache_scatter_kernel<<<(n4 + 255) / 256, 256>>>(k, v, slot, out_kc, out_vc);

    dim3 grid(kS / BM, kH, kB);
    attn_kernel<<<grid, NT, SMEM_BYTES>>>(q, k, v, out_o);
}

// round 4
// speedup vs baseline: 3.2309x; 3.2309x over previous
#include <cuda_runtime.h>
#include <cuda_bf16.h>

// Problem constants
constexpr int kB = 2, kS = 2048, kH = 32, kHK = 8, kD = 128;
constexpr int kG  = kH / kHK;     // 4
constexpr int kN  = kB * kS;      // 4096
constexpr int kHD = kH * kD;      // 4096
constexpr int kHKD = kHK * kD;    // 1024
constexpr float kScale = 0.08838834764831845f;           // 1/sqrt(128)
constexpr float kSc2   = kScale * 1.4426950408889634f;   // scale * log2(e)

// Tiling
constexpr int BM = 64, BN = 64, NT = 128;
constexpr int KP = 136;  // bf16 pitch for Q,K tiles (conflict-free frag LDS)
constexpr int VP = 72;   // bf16 pitch for Vt tile
constexpr int SMEM_BF16 = 2 * (BM * KP) + 2 * (BN * KP) + 2 * (kD * VP);
constexpr int SMEM_BYTES = SMEM_BF16 * 2;  // 106496 B -> 2 CTAs/SM

// bf16 hi/lo scratch: K in source layout, V transposed [bh][d][s]
__device__ __nv_bfloat16 g_Khi[(size_t)kN * kHKD];
__device__ __nv_bfloat16 g_Klo[(size_t)kN * kHKD];
__device__ __nv_bfloat16 g_Vthi[(size_t)kN * kHKD];
__device__ __nv_bfloat16 g_Vtlo[(size_t)kN * kHKD];

// ---------------------------------------------------------------------------
// KV-cache output (unchanged)
// ---------------------------------------------------------------------------
__global__ void cache_copy_kernel(const float* __restrict__ kc,
                                  const float* __restrict__ vc,
                                  float* __restrict__ okc,
                                  float* __restrict__ ovc) {
    int i = blockIdx.x * blockDim.x + threadIdx.x;
    int n4 = kN * kHKD / 4;
    if (i < n4) {
        reinterpret_cast<float4*>(okc)[i] = reinterpret_cast<const float4*>(kc)[i];
        reinterpret_cast<float4*>(ovc)[i] = reinterpret_cast<const float4*>(vc)[i];
    }
}

__global__ void cache_scatter_kernel(const float* __restrict__ k,
                                     const float* __restrict__ v,
                                     const int* __restrict__ slot,
                                     float* __restrict__ okc,
                                     float* __restrict__ ovc) {
    int i = blockIdx.x * blockDim.x + threadIdx.x;
    constexpr int per_row = kHKD / 4;
    int n4 = kN * per_row;
    if (i < n4) {
        int n = i / per_row;
        int c = i - n * per_row;
        int s = slot[n];
        if (s >= 0 && s < kN) {
            reinterpret_cast<float4*>(okc)[s * per_row + c] =
                reinterpret_cast<const float4*>(k)[i];
            reinterpret_cast<float4*>(ovc)[s * per_row + c] =
                reinterpret_cast<const float4*>(v)[i];
        }
    }
}

// ---------------------------------------------------------------------------
// Prep: split K into bf16 hi/lo (same layout as source)
// ---------------------------------------------------------------------------
__global__ void ksplit_kernel(const float* __restrict__ k) {
    int i = blockIdx.x * blockDim.x + threadIdx.x;  // float4 index
    int n4 = kN * kHKD / 4;
    if (i >= n4) return;
    float4 f = reinterpret_cast<const float4*>(k)[i];
    __nv_bfloat162 h0 = __floats2bfloat162_rn(f.x, f.y);
    __nv_bfloat162 h1 = __floats2bfloat162_rn(f.z, f.w);
    __nv_bfloat162 l0 = __floats2bfloat162_rn(f.x - __bfloat162float(h0.x),
                                              f.y - __bfloat162float(h0.y));
    __nv_bfloat162 l1 = __floats2bfloat162_rn(f.z - __bfloat162float(h1.x),
                                              f.w - __bfloat162float(h1.y));
    reinterpret_cast<__nv_bfloat162*>(g_Khi)[2 * i]     = h0;
    reinterpret_cast<__nv_bfloat162*>(g_Khi)[2 * i + 1] = h1;
    reinterpret_cast<__nv_bfloat162*>(g_Klo)[2 * i]     = l0;
    reinterpret_cast<__nv_bfloat162*>(g_Klo)[2 * i + 1] = l1;
}

// Prep: split + transpose V -> Vt[bh][d][s]
__global__ void vtrans_kernel(const float* __restrict__ v) {
    __shared__ __nv_bfloat16 th[32][33];
    __shared__ __nv_bfloat16 tl[32][33];
    int bh = blockIdx.z;
    int d0 = blockIdx.y * 32, s0 = blockIdx.x * 32;
    int b = bh >> 3, hk = bh & 7;
    int tx = threadIdx.x, ty = threadIdx.y;
    float x = v[((size_t)(b * kS + s0 + ty) * kHK + hk) * kD + d0 + tx];
    __nv_bfloat16 h = __float2bfloat16(x);
    th[ty][tx] = h;
    tl[ty][tx] = __float2bfloat16(x - __bfloat162float(h));
    __syncthreads();
    size_t oi = ((size_t)(bh * kD + d0 + ty)) * kS + s0 + tx;
    g_Vthi[oi] = th[tx][ty];
    g_Vtlo[oi] = tl[tx][ty];
}

// ---------------------------------------------------------------------------
// mma.sync m16n8k16 bf16 helpers
// ---------------------------------------------------------------------------
__device__ __forceinline__ void mma16816(float* d,
                                         unsigned a0, unsigned a1, unsigned a2, unsigned a3,
                                         unsigned b0, unsigned b1) {
    asm volatile(
        "mma.sync.aligned.m16n8k16.row.col.f32.bf16.bf16.f32 "
        "{%0,%1,%2,%3},{%4,%5,%6,%7},{%8,%9},{%0,%1,%2,%3};\n"
        : "+f"(d[0]), "+f"(d[1]), "+f"(d[2]), "+f"(d[3])
        : "r"(a0), "r"(a1), "r"(a2), "r"(a3), "r"(b0), "r"(b1));
}

__device__ __forceinline__ unsigned pk2(float x, float y) {
    __nv_bfloat162 t = __floats2bfloat162_rn(x, y);
    return *reinterpret_cast<unsigned*>(&t);
}
__device__ __forceinline__ unsigned pk2lo(float x, float y, unsigned hi) {
    __nv_bfloat162 h = *reinterpret_cast<__nv_bfloat162*>(&hi);
    return pk2(x - __bfloat162float(h.x), y - __bfloat162float(h.y));
}

// ---------------------------------------------------------------------------
// Flash attention, bf16x3 split-precision tensor cores, online softmax.
// Grid (S/BM, H, B), 128 threads; warp w owns rows [16w,16w+16) full width.
// ---------------------------------------------------------------------------
__global__ __launch_bounds__(NT, 2)
void attn_kernel(const float* __restrict__ q, float* __restrict__ o) {
    extern __shared__ __nv_bfloat16 sm[];
    __nv_bfloat16* sQh = sm;                 // [64][136]
    __nv_bfloat16* sQl = sQh + BM * KP;
    __nv_bfloat16* sKh = sQl + BM * KP;      // [64][136]
    __nv_bfloat16* sKl = sKh + BN * KP;
    __nv_bfloat16* sVh = sKl + BN * KP;      // [128][72] (d-major, keys contiguous)
    __nv_bfloat16* sVl = sVh + kD * VP;

    const int tid = threadIdx.x;
    const int w = tid >> 5;
    const int lane = tid & 31;
    const int qd = lane >> 2;   // 0..7 (row-in-tile / n-in-tile)
    const int qp = lane & 3;    // 0..3 (k-pair selector)
    const int qb = blockIdx.x, h = blockIdx.y, b = blockIdx.z;
    const int hk = h >> 2;
    const int bh = b * kHK + hk;

    // ---- Q load + hi/lo split into smem ----
    const float* qbase = q + ((size_t)(b * kS + qb * BM)) * kHD + h * kD;
    #pragma unroll
    for (int it = 0; it < 16; ++it) {
        int idx = it * NT + tid;      // 0..2047 float4s
        int r = idx >> 5, c = idx & 31;
        float4 f = *reinterpret_cast<const float4*>(qbase + (size_t)r * kHD + c * 4);
        __nv_bfloat162 h0 = __floats2bfloat162_rn(f.x, f.y);
        __nv_bfloat162 h1 = __floats2bfloat162_rn(f.z, f.w);
        __nv_bfloat162 l0 = __floats2bfloat162_rn(f.x - __bfloat162float(h0.x),
                                                  f.y - __bfloat162float(h0.y));
        __nv_bfloat162 l1 = __floats2bfloat162_rn(f.z - __bfloat162float(h1.x),
                                                  f.w - __bfloat162float(h1.y));
        *reinterpret_cast<__nv_bfloat162*>(&sQh[r * KP + c * 4])     = h0;
        *reinterpret_cast<__nv_bfloat162*>(&sQh[r * KP + c * 4 + 2]) = h1;
        *reinterpret_cast<__nv_bfloat162*>(&sQl[r * KP + c * 4])     = l0;
        *reinterpret_cast<__nv_bfloat162*>(&sQl[r * KP + c * 4 + 2]) = l1;
    }

    float o_[16][4];
    #pragma unroll
    for (int j = 0; j < 16; ++j)
        #pragma unroll
        for (int e = 0; e < 4; ++e) o_[j][e] = 0.f;
    float m0 = -1e30f, m1 = -1e30f, l0 = 0.f, l1 = 0.f;

    const int arow = w * 16 + qd;        // local row (pair +8)

    for (int kt = 0; kt <= qb; ++kt) {
        __syncthreads();
        // ---- load K tile (hi/lo) ----
        const size_t krow0 = ((size_t)(b * kS + kt * BN)) * kHKD + hk * kD;
        #pragma unroll
        for (int it = 0; it < 8; ++it) {
            int idx = it * NT + tid;     // 0..1023
            int r = idx >> 4, c = idx & 15;
            const uint4* ph = reinterpret_cast<const uint4*>(g_Khi + krow0 + (size_t)r * kHKD);
            const uint4* pl = reinterpret_cast<const uint4*>(g_Klo + krow0 + (size_t)r * kHKD);
            *reinterpret_cast<uint4*>(&sKh[r * KP + c * 8]) = ph[c];
            *reinterpret_cast<uint4*>(&sKl[r * KP + c * 8]) = pl[c];
        }
        // ---- load Vt tile (hi/lo) ----
        const size_t vrow0 = ((size_t)bh * kD) * kS + (size_t)kt * BN;
        #pragma unroll
        for (int it = 0; it < 8; ++it) {
            int idx = it * NT + tid;     // 0..1023
            int r = idx >> 3, c = idx & 7;   // r = d row, c = 8-key chunk
            const uint4* ph = reinterpret_cast<const uint4*>(g_Vthi + vrow0 + (size_t)r * kS);
            const uint4* pl = reinterpret_cast<const uint4*>(g_Vtlo + vrow0 + (size_t)r * kS);
            *reinterpret_cast<uint4*>(&sVh[r * VP + c * 8]) = ph[c];
            *reinterpret_cast<uint4*>(&sVl[r * VP + c * 8]) = pl[c];
        }
        __syncthreads();

        // ---- S = Q K^T  (bf16x3) ----
        float s_[8][4];
        #pragma unroll
        for (int j = 0; j < 8; ++j)
            #pragma unroll
            for (int e = 0; e < 4; ++e) s_[j][e] = 0.f;

        #pragma unroll
        for (int c = 0; c < 8; ++c) {
            int k0 = c * 16 + qp * 2;
            unsigned ah0 = *reinterpret_cast<const unsigned*>(&sQh[ arow      * KP + k0]);
            unsigned ah1 = *reinterpret_cast<const unsigned*>(&sQh[(arow + 8) * KP + k0]);
            unsigned ah2 = *reinterpret_cast<const unsigned*>(&sQh[ arow      * KP + k0 + 8]);
            unsigned ah3 = *reinterpret_cast<const unsigned*>(&sQh[(arow + 8) * KP + k0 + 8]);
            unsigned al0 = *reinterpret_cast<const unsigned*>(&sQl[ arow      * KP + k0]);
            unsigned al1 = *reinterpret_cast<const unsigned*>(&sQl[(arow + 8) * KP + k0]);
            unsigned al2 = *reinterpret_cast<const unsigned*>(&sQl[ arow      * KP + k0 + 8]);
            unsigned al3 = *reinterpret_cast<const unsigned*>(&sQl[(arow + 8) * KP + k0 + 8]);
            #pragma unroll
            for (int j = 0; j < 8; ++j) {
                int br = j * 8 + qd;
                unsigned bh0 = *reinterpret_cast<const unsigned*>(&sKh[br * KP + k0]);
                unsigned bh1 = *reinterpret_cast<const unsigned*>(&sKh[br * KP + k0 + 8]);
                unsigned bl0 = *reinterpret_cast<const unsigned*>(&sKl[br * KP + k0]);
                unsigned bl1 = *reinterpret_cast<const unsigned*>(&sKl[br * KP + k0 + 8]);
                mma16816(s_[j], ah0, ah1, ah2, ah3, bh0, bh1);
                mma16816(s_[j], ah0, ah1, ah2, ah3, bl0, bl1);
                mma16816(s_[j], al0, al1, al2, al3, bh0, bh1);
            }
        }

        // ---- online softmax (base-2, register-resident) ----
        const bool diag = (kt == qb);
        float mx0 = -1e30f, mx1 = -1e30f;
        #pragma unroll
        for (int j = 0; j < 8; ++j) {
            int cl = j * 8 + qp * 2;
            float v0 = s_[j][0] * kSc2, v1 = s_[j][1] * kSc2;
            float v2 = s_[j][2] * kSc2, v3 = s_[j][3] * kSc2;
            if (diag) {
                if (cl     > arow)     v0 = -1e30f;
                if (cl + 1 > arow)     v1 = -1e30f;
                if (cl     > arow + 8) v2 = -1e30f;
                if (cl + 1 > arow + 8) v3 = -1e30f;
            }
            s_[j][0] = v0; s_[j][1] = v1; s_[j][2] = v2; s_[j][3] = v3;
            mx0 = fmaxf(mx0, fmaxf(v0, v1));
            mx1 = fmaxf(mx1, fmaxf(v2, v3));
        }
        mx0 = fmaxf(mx0, __shfl_xor_sync(0xffffffffu, mx0, 1));
        mx0 = fmaxf(mx0, __shfl_xor_sync(0xffffffffu, mx0, 2));
        mx1 = fmaxf(mx1, __shfl_xor_sync(0xffffffffu, mx1, 1));
        mx1 = fmaxf(mx1, __shfl_xor_sync(0xffffffffu, mx1, 2));
        float mn0 = fmaxf(m0, mx0), mn1 = fmaxf(m1, mx1);
        float al0 = exp2f(m0 - mn0), al1 = exp2f(m1 - mn1);
        m0 = mn0; m1 = mn1;
        float rs0 = 0.f, rs1 = 0.f;
        #pragma unroll
        for (int j = 0; j < 8; ++j) {
            float p0 = exp2f(s_[j][0] - mn0);
            float p1 = exp2f(s_[j][1] - mn0);
            float p2 = exp2f(s_[j][2] - mn1);
            float p3 = exp2f(s_[j][3] - mn1);
            rs0 += p0 + p1; rs1 += p2 + p3;
            s_[j][0] = p0; s_[j][1] = p1; s_[j][2] = p2; s_[j][3] = p3;
        }
        rs0 += __shfl_xor_sync(0xffffffffu, rs0, 1);
        rs0 += __shfl_xor_sync(0xffffffffu, rs0, 2);
        rs1 += __shfl_xor_sync(0xffffffffu, rs1, 1);
        rs1 += __shfl_xor_sync(0xffffffffu, rs1, 2);
        l0 = l0 * al0 + rs0;
        l1 = l1 * al1 + rs1;

        // rescale running O
        #pragma unroll
        for (int j = 0; j < 16; ++j) {
            o_[j][0] *= al0; o_[j][1] *= al0;
            o_[j][2] *= al1; o_[j][3] *= al1;
        }

        // ---- O += P V  (bf16x3; P packed from accumulators per k-chunk) ----
        #pragma unroll
        for (int cc = 0; cc < 4; ++cc) {
            unsigned ph0 = pk2(s_[2 * cc][0], s_[2 * cc][1]);
            unsigned ph1 = pk2(s_[2 * cc][2], s_[2 * cc][3]);
            unsigned ph2 = pk2(s_[2 * cc + 1][0], s_[2 * cc + 1][1]);
            unsigned ph3 = pk2(s_[2 * cc + 1][2], s_[2 * cc + 1][3]);
            unsigned pl0 = pk2lo(s_[2 * cc][0], s_[2 * cc][1], ph0);
            unsigned pl1 = pk2lo(s_[2 * cc][2], s_[2 * cc][3], ph1);
            unsigned pl2 = pk2lo(s_[2 * cc + 1][0], s_[2 * cc + 1][1], ph2);
            unsigned pl3 = pk2lo(s_[2 * cc + 1][2], s_[2 * cc + 1][3], ph3);
            int k0 = cc * 16 + qp * 2;
            #pragma unroll
            for (int j = 0; j < 16; ++j) {
                int br = j * 8 + qd;   // d index
                unsigned bh0 = *reinterpret_cast<const unsigned*>(&sVh[br * VP + k0]);
                unsigned bh1 = *reinterpret_cast<const unsigned*>(&sVh[br * VP + k0 + 8]);
                unsigned bl0 = *reinterpret_cast<const unsigned*>(&sVl[br * VP + k0]);
                unsigned bl1 = *reinterpret_cast<const unsigned*>(&sVl[br * VP + k0 + 8]);
                mma16816(o_[j], ph0, ph1, ph2, ph3, bh0, bh1);
                mma16816(o_[j], ph0, ph1, ph2, ph3, bl0, bl1);
                mma16816(o_[j], pl0, pl1, pl2, pl3, bh0, bh1);
            }
        }
    }

    // ---- epilogue ----
    float inv0 = 1.0f / l0, inv1 = 1.0f / l1;
    float* obase = o + ((size_t)(b * kS + qb * BM + w * 16)) * kHD + h * kD;
    #pragma unroll
    for (int j = 0; j < 16; ++j) {
        int dcol = j * 8 + qp * 2;
        float2 r0 = {o_[j][0] * inv0, o_[j][1] * inv0};
        float2 r1 = {o_[j][2] * inv1, o_[j][3] * inv1};
        *reinterpret_cast<float2*>(obase + (size_t)qd * kHD + dcol)       = r0;
        *reinterpret_cast<float2*>(obase + (size_t)(qd + 8) * kHD + dcol) = r1;
    }
}

// ---------------------------------------------------------------------------
// Launch
// ---------------------------------------------------------------------------
extern "C" void kernel_launch(void* const* d_in, const int* in_sizes, int n_in,
                              void* d_out, int out_size) {
    const float* q    = (const float*)d_in[0];
    const float* k    = (const float*)d_in[1];
    const float* v    = (const float*)d_in[2];
    const float* kc   = (const float*)d_in[3];
    const float* vc   = (const float*)d_in[4];
    const int*   slot = (const int*)d_in[5];

    float* out    = (float*)d_out;
    float* out_o  = out;
    float* out_kc = out + (size_t)kN * kHD;
    float* out_vc = out_kc + (size_t)kN * kHKD;

    cudaFuncSetAttribute(attn_kernel,
                         cudaFuncAttributeMaxDynamicSharedMemorySize, SMEM_BYTES);

    int n4 = kN * kHKD / 4;
    cache_copy_kernel<<<(n4 + 255) / 256, 256>>>(kc, vc, out_kc, out_vc);
    cache_scatter_kernel<<<(n4 + 255) / 256, 256>>>(k, v, slot, out_kc, out_vc);

    ksplit_kernel<<<(n4 + 255) / 256, 256>>>(k);
    dim3 vg(kS / 32, kD / 32, kB * kHK);
    vtrans_kernel<<<vg, dim3(32, 32)>>>(v);

    dim3 grid(kS / BM, kH, kB);
    attn_kernel<<<grid, NT, SMEM_BYTES>>>(q, out_o);
}

// round 5
// speedup vs baseline: 3.7228x; 1.1523x over previous
#include <cuda_runtime.h>
#include <cuda_bf16.h>

// Problem constants
constexpr int kB = 2, kS = 2048, kH = 32, kHK = 8, kD = 128;
constexpr int kG  = kH / kHK;     // 4
constexpr int kN  = kB * kS;      // 4096
constexpr int kHD = kH * kD;      // 4096
constexpr int kHKD = kHK * kD;    // 1024
constexpr float kScale = 0.08838834764831845f;           // 1/sqrt(128)
constexpr float kSc2   = kScale * 1.4426950408889634f;   // scale * log2(e)

// Tiling
constexpr int BM = 64, BN = 64, NT = 128;
constexpr int KP = 136;  // bf16 pitch for Q,K tiles (conflict-free LDSM: +4 banks/row)
constexpr int VP = 72;   // bf16 pitch for Vt tile
constexpr int SMEM_BF16 = 2 * (BM * KP) + 2 * (BN * KP) + 2 * (kD * VP);
constexpr int SMEM_BYTES = SMEM_BF16 * 2;  // 106496 B -> 2 CTAs/SM

// bf16 hi/lo scratch: K in source layout, V transposed [bh][d][s]
__device__ __nv_bfloat16 g_Khi[(size_t)kN * kHKD];
__device__ __nv_bfloat16 g_Klo[(size_t)kN * kHKD];
__device__ __nv_bfloat16 g_Vthi[(size_t)kN * kHKD];
__device__ __nv_bfloat16 g_Vtlo[(size_t)kN * kHKD];

// ---------------------------------------------------------------------------
// KV-cache output (copy split in two so attn_kernel is the 6th launch -> ncu
// -s 5 -c 1 captures it)
// ---------------------------------------------------------------------------
__global__ void cache_copy_k_kernel(const float* __restrict__ kc,
                                    float* __restrict__ okc) {
    int i = blockIdx.x * blockDim.x + threadIdx.x;
    int n4 = kN * kHKD / 4;
    if (i < n4)
        reinterpret_cast<float4*>(okc)[i] = reinterpret_cast<const float4*>(kc)[i];
}
__global__ void cache_copy_v_kernel(const float* __restrict__ vc,
                                    float* __restrict__ ovc) {
    int i = blockIdx.x * blockDim.x + threadIdx.x;
    int n4 = kN * kHKD / 4;
    if (i < n4)
        reinterpret_cast<float4*>(ovc)[i] = reinterpret_cast<const float4*>(vc)[i];
}

__global__ void cache_scatter_kernel(const float* __restrict__ k,
                                     const float* __restrict__ v,
                                     const int* __restrict__ slot,
                                     float* __restrict__ okc,
                                     float* __restrict__ ovc) {
    int i = blockIdx.x * blockDim.x + threadIdx.x;
    constexpr int per_row = kHKD / 4;
    int n4 = kN * per_row;
    if (i < n4) {
        int n = i / per_row;
        int c = i - n * per_row;
        int s = slot[n];
        if (s >= 0 && s < kN) {
            reinterpret_cast<float4*>(okc)[s * per_row + c] =
                reinterpret_cast<const float4*>(k)[i];
            reinterpret_cast<float4*>(ovc)[s * per_row + c] =
                reinterpret_cast<const float4*>(v)[i];
        }
    }
}

// ---------------------------------------------------------------------------
// Prep: split K into bf16 hi/lo (same layout as source)
// ---------------------------------------------------------------------------
__global__ void ksplit_kernel(const float* __restrict__ k) {
    int i = blockIdx.x * blockDim.x + threadIdx.x;  // float4 index
    int n4 = kN * kHKD / 4;
    if (i >= n4) return;
    float4 f = reinterpret_cast<const float4*>(k)[i];
    __nv_bfloat162 h0 = __floats2bfloat162_rn(f.x, f.y);
    __nv_bfloat162 h1 = __floats2bfloat162_rn(f.z, f.w);
    __nv_bfloat162 l0 = __floats2bfloat162_rn(f.x - __bfloat162float(h0.x),
                                              f.y - __bfloat162float(h0.y));
    __nv_bfloat162 l1 = __floats2bfloat162_rn(f.z - __bfloat162float(h1.x),
                                              f.w - __bfloat162float(h1.y));
    reinterpret_cast<__nv_bfloat162*>(g_Khi)[2 * i]     = h0;
    reinterpret_cast<__nv_bfloat162*>(g_Khi)[2 * i + 1] = h1;
    reinterpret_cast<__nv_bfloat162*>(g_Klo)[2 * i]     = l0;
    reinterpret_cast<__nv_bfloat162*>(g_Klo)[2 * i + 1] = l1;
}

// Prep: split + transpose V -> Vt[bh][d][s]
__global__ void vtrans_kernel(const float* __restrict__ v) {
    __shared__ __nv_bfloat16 th[32][33];
    __shared__ __nv_bfloat16 tl[32][33];
    int bh = blockIdx.z;
    int d0 = blockIdx.y * 32, s0 = blockIdx.x * 32;
    int b = bh >> 3, hk = bh & 7;
    int tx = threadIdx.x, ty = threadIdx.y;
    float x = v[((size_t)(b * kS + s0 + ty) * kHK + hk) * kD + d0 + tx];
    __nv_bfloat16 h = __float2bfloat16(x);
    th[ty][tx] = h;
    tl[ty][tx] = __float2bfloat16(x - __bfloat162float(h));
    __syncthreads();
    size_t oi = ((size_t)(bh * kD + d0 + ty)) * kS + s0 + tx;
    g_Vthi[oi] = th[tx][ty];
    g_Vtlo[oi] = tl[tx][ty];
}

// ---------------------------------------------------------------------------
// PTX helpers
// ---------------------------------------------------------------------------
__device__ __forceinline__ void mma16816(float* d,
                                         unsigned a0, unsigned a1, unsigned a2, unsigned a3,
                                         unsigned b0, unsigned b1) {
    asm volatile(
        "mma.sync.aligned.m16n8k16.row.col.f32.bf16.bf16.f32 "
        "{%0,%1,%2,%3},{%4,%5,%6,%7},{%8,%9},{%0,%1,%2,%3};\n"
        : "+f"(d[0]), "+f"(d[1]), "+f"(d[2]), "+f"(d[3])
        : "r"(a0), "r"(a1), "r"(a2), "r"(a3), "r"(b0), "r"(b1));
}

__device__ __forceinline__ void ldsm4(unsigned& r0, unsigned& r1,
                                      unsigned& r2, unsigned& r3, unsigned a) {
    asm volatile("ldmatrix.sync.aligned.m8n8.x4.shared.b16 {%0,%1,%2,%3}, [%4];\n"
                 : "=r"(r0), "=r"(r1), "=r"(r2), "=r"(r3) : "r"(a));
}

__device__ __forceinline__ void cp16(unsigned dst, const void* src) {
    asm volatile("cp.async.cg.shared.global [%0], [%1], 16;\n" :: "r"(dst), "l"(src));
}
__device__ __forceinline__ void cp_commit_wait() {
    asm volatile("cp.async.commit_group;\ncp.async.wait_group 0;\n" ::: "memory");
}

__device__ __forceinline__ unsigned pk2(float x, float y) {
    __nv_bfloat162 t = __floats2bfloat162_rn(x, y);
    return *reinterpret_cast<unsigned*>(&t);
}
__device__ __forceinline__ unsigned pk2lo(float x, float y, unsigned hi) {
    __nv_bfloat162 h = *reinterpret_cast<__nv_bfloat162*>(&hi);
    return pk2(x - __bfloat162float(h.x), y - __bfloat162float(h.y));
}

// ---------------------------------------------------------------------------
// Flash attention, bf16x3 split tensor cores; Q frags register-resident,
// K/V frags via ldmatrix.x4, tile copies via cp.async.
// Grid (S/BM, H, B), 128 threads; warp w owns rows [16w,16w+16).
// ---------------------------------------------------------------------------
__global__ __launch_bounds__(NT, 2)
void attn_kernel(const float* __restrict__ q, float* __restrict__ o) {
    extern __shared__ __nv_bfloat16 sm[];
    __nv_bfloat16* sQh = sm;                 // [64][136]
    __nv_bfloat16* sQl = sQh + BM * KP;
    __nv_bfloat16* sKh = sQl + BM * KP;      // [64][136]
    __nv_bfloat16* sKl = sKh + BN * KP;
    __nv_bfloat16* sVh = sKl + BN * KP;      // [128][72]
    __nv_bfloat16* sVl = sVh + kD * VP;

    const int tid = threadIdx.x;
    const int w = tid >> 5;
    const int lane = tid & 31;
    const int qd = lane >> 2;   // 0..7
    const int qp = lane & 3;    // 0..3
    const int qb = blockIdx.x, h = blockIdx.y, b = blockIdx.z;
    const int hk = h >> 2;
    const int bh = b * kHK + hk;
    const int arow = w * 16 + qd;

    // ldmatrix per-lane relative offsets (bytes): row_rel in [0,16), col_rel {0,8}
    const int lrow = ((lane >> 4) << 3) + (lane & 7);
    const int lcol = ((lane >> 3) & 1) << 3;
    const unsigned uKh = (unsigned)__cvta_generic_to_shared(sKh) + (unsigned)((lrow * KP + lcol) * 2);
    const unsigned uKl = (unsigned)__cvta_generic_to_shared(sKl) + (unsigned)((lrow * KP + lcol) * 2);
    const unsigned uVh = (unsigned)__cvta_generic_to_shared(sVh) + (unsigned)((lrow * VP + lcol) * 2);
    const unsigned uVl = (unsigned)__cvta_generic_to_shared(sVl) + (unsigned)((lrow * VP + lcol) * 2);

    // ---- Q load + hi/lo split into smem ----
    const float* qbase = q + ((size_t)(b * kS + qb * BM)) * kHD + h * kD;
    #pragma unroll
    for (int it = 0; it < 16; ++it) {
        int idx = it * NT + tid;      // 0..2047 float4s
        int r = idx >> 5, c = idx & 31;
        float4 f = *reinterpret_cast<const float4*>(qbase + (size_t)r * kHD + c * 4);
        __nv_bfloat162 h0 = __floats2bfloat162_rn(f.x, f.y);
        __nv_bfloat162 h1 = __floats2bfloat162_rn(f.z, f.w);
        __nv_bfloat162 l0 = __floats2bfloat162_rn(f.x - __bfloat162float(h0.x),
                                                  f.y - __bfloat162float(h0.y));
        __nv_bfloat162 l1 = __floats2bfloat162_rn(f.z - __bfloat162float(h1.x),
                                                  f.w - __bfloat162float(h1.y));
        *reinterpret_cast<__nv_bfloat162*>(&sQh[r * KP + c * 4])     = h0;
        *reinterpret_cast<__nv_bfloat162*>(&sQh[r * KP + c * 4 + 2]) = h1;
        *reinterpret_cast<__nv_bfloat162*>(&sQl[r * KP + c * 4])     = l0;
        *reinterpret_cast<__nv_bfloat162*>(&sQl[r * KP + c * 4 + 2]) = l1;
    }
    __syncthreads();

    // ---- hoist Q fragments to registers (loop-invariant) ----
    unsigned ah[8][4], al[8][4];
    #pragma unroll
    for (int c = 0; c < 8; ++c) {
        int k0 = c * 16 + qp * 2;
        ah[c][0] = *reinterpret_cast<const unsigned*>(&sQh[ arow      * KP + k0]);
        ah[c][1] = *reinterpret_cast<const unsigned*>(&sQh[(arow + 8) * KP + k0]);
        ah[c][2] = *reinterpret_cast<const unsigned*>(&sQh[ arow      * KP + k0 + 8]);
        ah[c][3] = *reinterpret_cast<const unsigned*>(&sQh[(arow + 8) * KP + k0 + 8]);
        al[c][0] = *reinterpret_cast<const unsigned*>(&sQl[ arow      * KP + k0]);
        al[c][1] = *reinterpret_cast<const unsigned*>(&sQl[(arow + 8) * KP + k0]);
        al[c][2] = *reinterpret_cast<const unsigned*>(&sQl[ arow      * KP + k0 + 8]);
        al[c][3] = *reinterpret_cast<const unsigned*>(&sQl[(arow + 8) * KP + k0 + 8]);
    }

    float o_[16][4];
    #pragma unroll
    for (int j = 0; j < 16; ++j)
        #pragma unroll
        for (int e = 0; e < 4; ++e) o_[j][e] = 0.f;
    float m0 = -1e30f, m1 = -1e30f, l0 = 0.f, l1 = 0.f;

    for (int kt = 0; kt <= qb; ++kt) {
        __syncthreads();  // protect sK/sV from previous iteration's readers

        // ---- cp.async tile loads: K (hi/lo) and Vt (hi/lo) ----
        const size_t krow0 = ((size_t)(b * kS + kt * BN)) * kHKD + hk * kD;
        const size_t vrow0 = ((size_t)bh * kD) * kS + (size_t)kt * BN;
        unsigned dKh = (unsigned)__cvta_generic_to_shared(sKh);
        unsigned dKl = (unsigned)__cvta_generic_to_shared(sKl);
        unsigned dVh = (unsigned)__cvta_generic_to_shared(sVh);
        unsigned dVl = (unsigned)__cvta_generic_to_shared(sVl);
        #pragma unroll
        for (int it = 0; it < 8; ++it) {
            int idx = it * NT + tid;     // 0..1023
            int r = idx >> 4, c = idx & 15;
            unsigned doff = (unsigned)((r * KP + c * 8) * 2);
            cp16(dKh + doff, g_Khi + krow0 + (size_t)r * kHKD + c * 8);
            cp16(dKl + doff, g_Klo + krow0 + (size_t)r * kHKD + c * 8);
        }
        #pragma unroll
        for (int it = 0; it < 8; ++it) {
            int idx = it * NT + tid;     // 0..1023
            int r = idx >> 3, c = idx & 7;
            unsigned doff = (unsigned)((r * VP + c * 8) * 2);
            cp16(dVh + doff, g_Vthi + vrow0 + (size_t)r * kS + c * 8);
            cp16(dVl + doff, g_Vtlo + vrow0 + (size_t)r * kS + c * 8);
        }
        cp_commit_wait();
        __syncthreads();

        // ---- S = Q K^T  (bf16x3, ldmatrix B) ----
        float s_[8][4];
        #pragma unroll
        for (int j = 0; j < 8; ++j)
            #pragma unroll
            for (int e = 0; e < 4; ++e) s_[j][e] = 0.f;

        #pragma unroll
        for (int c = 0; c < 8; ++c) {
            #pragma unroll
            for (int jp = 0; jp < 4; ++jp) {
                unsigned koff = (unsigned)((jp * 16 * KP + c * 16) * 2);
                unsigned bh0, bh1, bh2, bh3, bl0, bl1, bl2, bl3;
                ldsm4(bh0, bh1, bh2, bh3, uKh + koff);
                ldsm4(bl0, bl1, bl2, bl3, uKl + koff);
                mma16816(s_[2 * jp],     ah[c][0], ah[c][1], ah[c][2], ah[c][3], bh0, bh1);
                mma16816(s_[2 * jp],     ah[c][0], ah[c][1], ah[c][2], ah[c][3], bl0, bl1);
                mma16816(s_[2 * jp],     al[c][0], al[c][1], al[c][2], al[c][3], bh0, bh1);
                mma16816(s_[2 * jp + 1], ah[c][0], ah[c][1], ah[c][2], ah[c][3], bh2, bh3);
                mma16816(s_[2 * jp + 1], ah[c][0], ah[c][1], ah[c][2], ah[c][3], bl2, bl3);
                mma16816(s_[2 * jp + 1], al[c][0], al[c][1], al[c][2], al[c][3], bh2, bh3);
            }
        }

        // ---- online softmax (base-2, register-resident) ----
        const bool diag = (kt == qb);
        float mx0 = -1e30f, mx1 = -1e30f;
        #pragma unroll
        for (int j = 0; j < 8; ++j) {
            int cl = j * 8 + qp * 2;
            float v0 = s_[j][0] * kSc2, v1 = s_[j][1] * kSc2;
            float v2 = s_[j][2] * kSc2, v3 = s_[j][3] * kSc2;
            if (diag) {
                if (cl     > arow)     v0 = -1e30f;
                if (cl + 1 > arow)     v1 = -1e30f;
                if (cl     > arow + 8) v2 = -1e30f;
                if (cl + 1 > arow + 8) v3 = -1e30f;
            }
            s_[j][0] = v0; s_[j][1] = v1; s_[j][2] = v2; s_[j][3] = v3;
            mx0 = fmaxf(mx0, fmaxf(v0, v1));
            mx1 = fmaxf(mx1, fmaxf(v2, v3));
        }
        mx0 = fmaxf(mx0, __shfl_xor_sync(0xffffffffu, mx0, 1));
        mx0 = fmaxf(mx0, __shfl_xor_sync(0xffffffffu, mx0, 2));
        mx1 = fmaxf(mx1, __shfl_xor_sync(0xffffffffu, mx1, 1));
        mx1 = fmaxf(mx1, __shfl_xor_sync(0xffffffffu, mx1, 2));
        float mn0 = fmaxf(m0, mx0), mn1 = fmaxf(m1, mx1);
        float a0 = exp2f(m0 - mn0), a1 = exp2f(m1 - mn1);
        m0 = mn0; m1 = mn1;
        float rs0 = 0.f, rs1 = 0.f;
        #pragma unroll
        for (int j = 0; j < 8; ++j) {
            float p0 = exp2f(s_[j][0] - mn0);
            float p1 = exp2f(s_[j][1] - mn0);
            float p2 = exp2f(s_[j][2] - mn1);
            float p3 = exp2f(s_[j][3] - mn1);
            rs0 += p0 + p1; rs1 += p2 + p3;
            s_[j][0] = p0; s_[j][1] = p1; s_[j][2] = p2; s_[j][3] = p3;
        }
        rs0 += __shfl_xor_sync(0xffffffffu, rs0, 1);
        rs0 += __shfl_xor_sync(0xffffffffu, rs0, 2);
        rs1 += __shfl_xor_sync(0xffffffffu, rs1, 1);
        rs1 += __shfl_xor_sync(0xffffffffu, rs1, 2);
        l0 = l0 * a0 + rs0;
        l1 = l1 * a1 + rs1;

        #pragma unroll
        for (int j = 0; j < 16; ++j) {
            o_[j][0] *= a0; o_[j][1] *= a0;
            o_[j][2] *= a1; o_[j][3] *= a1;
        }

        // ---- O += P V  (bf16x3, ldmatrix B) ----
        #pragma unroll
        for (int cc = 0; cc < 4; ++cc) {
            unsigned ph0 = pk2(s_[2 * cc][0], s_[2 * cc][1]);
            unsigned ph1 = pk2(s_[2 * cc][2], s_[2 * cc][3]);
            unsigned ph2 = pk2(s_[2 * cc + 1][0], s_[2 * cc + 1][1]);
            unsigned ph3 = pk2(s_[2 * cc + 1][2], s_[2 * cc + 1][3]);
            unsigned pl0 = pk2lo(s_[2 * cc][0], s_[2 * cc][1], ph0);
            unsigned pl1 = pk2lo(s_[2 * cc][2], s_[2 * cc][3], ph1);
            unsigned pl2 = pk2lo(s_[2 * cc + 1][0], s_[2 * cc + 1][1], ph2);
            unsigned pl3 = pk2lo(s_[2 * cc + 1][2], s_[2 * cc + 1][3], ph3);
            #pragma unroll
            for (int jp = 0; jp < 8; ++jp) {
                unsigned voff = (unsigned)((jp * 16 * VP + cc * 16) * 2);
                unsigned bh0, bh1, bh2, bh3, bl0, bl1, bl2, bl3;
                ldsm4(bh0, bh1, bh2, bh3, uVh + voff);
                ldsm4(bl0, bl1, bl2, bl3, uVl + voff);
                mma16816(o_[2 * jp],     ph0, ph1, ph2, ph3, bh0, bh1);
                mma16816(o_[2 * jp],     ph0, ph1, ph2, ph3, bl0, bl1);
                mma16816(o_[2 * jp],     pl0, pl1, pl2, pl3, bh0, bh1);
                mma16816(o_[2 * jp + 1], ph0, ph1, ph2, ph3, bh2, bh3);
                mma16816(o_[2 * jp + 1], ph0, ph1, ph2, ph3, bl2, bl3);
                mma16816(o_[2 * jp + 1], pl0, pl1, pl2, pl3, bh2, bh3);
            }
        }
    }

    // ---- epilogue ----
    float inv0 = 1.0f / l0, inv1 = 1.0f / l1;
    float* obase = o + ((size_t)(b * kS + qb * BM + w * 16)) * kHD + h * kD;
    #pragma unroll
    for (int j = 0; j < 16; ++j) {
        int dcol = j * 8 + qp * 2;
        float2 r0 = {o_[j][0] * inv0, o_[j][1] * inv0};
        float2 r1 = {o_[j][2] * inv1, o_[j][3] * inv1};
        *reinterpret_cast<float2*>(obase + (size_t)qd * kHD + dcol)       = r0;
        *reinterpret_cast<float2*>(obase + (size_t)(qd + 8) * kHD + dcol) = r1;
    }
}

// ---------------------------------------------------------------------------
// Launch (6 launches; attn_kernel is #6 so ncu -s 5 captures it)
// ---------------------------------------------------------------------------
extern "C" void kernel_launch(void* const* d_in, const int* in_sizes, int n_in,
                              void* d_out, int out_size) {
    const float* q    = (const float*)d_in[0];
    const float* k    = (const float*)d_in[1];
    const float* v    = (const float*)d_in[2];
    const float* kc   = (const float*)d_in[3];
    const float* vc   = (const float*)d_in[4];
    const int*   slot = (const int*)d_in[5];

    float* out    = (float*)d_out;
    float* out_o  = out;
    float* out_kc = out + (size_t)kN * kHD;
    float* out_vc = out_kc + (size_t)kN * kHKD;

    cudaFuncSetAttribute(attn_kernel,
                         cudaFuncAttributeMaxDynamicSharedMemorySize, SMEM_BYTES);

    int n4 = kN * kHKD / 4;
    cache_copy_k_kernel<<<(n4 + 255) / 256, 256>>>(kc, out_kc);
    cache_copy_v_kernel<<<(n4 + 255) / 256, 256>>>(vc, out_vc);
    cache_scatter_kernel<<<(n4 + 255) / 256, 256>>>(k, v, slot, out_kc, out_vc);

    ksplit_kernel<<<(n4 + 255) / 256, 256>>>(k);
    dim3 vg(kS / 32, kD / 32, kB * kHK);
    vtrans_kernel<<<vg, dim3(32, 32)>>>(v);

    dim3 grid(kS / BM, kH, kB);
    attn_kernel<<<grid, NT, SMEM_BYTES>>>(q, out_o);
}